// round 1
// baseline (speedup 1.0000x reference)
#include <cuda_runtime.h>
#include <math.h>

// Problem constants (fixed by the dataset)
static constexpr int Bb   = 8;
static constexpr int Cc   = 256;
static constexpr int Hh   = 64;
static constexpr int Ww   = 64;
static constexpr int Sp   = 1024;   // pooled spatial 32*32
static constexpr int NH   = 8;
static constexpr int HD   = 32;
static constexpr int PLANE = Cc * Sp;  // per-batch [C][S] plane

// Scratch (static device globals; allocation-free per harness rules)
__device__ float g_qp[Bb * PLANE];
__device__ float g_kp[Bb * PLANE];
__device__ float g_Q [Bb * PLANE];
__device__ float g_K [Bb * PLANE];
__device__ float g_V [Bb * PLANE];
__device__ float g_Os[Bb * PLANE];
__device__ float g_ys[Bb * PLANE];

// ---------------------------------------------------------------------------
// Kernel 1: AvgPool2d(2) for query and kv, layout [b][c][s], s = py*32+px
// ---------------------------------------------------------------------------
__global__ __launch_bounds__(256) void pool_kernel(const float* __restrict__ q,
                                                   const float* __restrict__ kv)
{
    int idx = blockIdx.x * blockDim.x + threadIdx.x;
    if (idx >= Bb * PLANE) return;
    int s  = idx & (Sp - 1);
    int px = s & 31;
    int py = s >> 5;
    int bc = idx >> 10;             // b*256 + c
    long off = ((long)bc * 64 + 2 * py) * 64 + 2 * px;

    float2 a0 = *(const float2*)(q + off);
    float2 a1 = *(const float2*)(q + off + 64);
    g_qp[idx] = 0.25f * (a0.x + a0.y + a1.x + a1.y);

    float2 b0 = *(const float2*)(kv + off);
    float2 b1 = *(const float2*)(kv + off + 64);
    g_kp[idx] = 0.25f * (b0.x + b0.y + b1.x + b1.y);
}

// ---------------------------------------------------------------------------
// Generic 128x128x8 fp32 tiled GEMM body:
//   Y[o][s] = sum_c W[o][c] * X[c][s],  M=256 (o), N=1024 (s), K=256 (c)
//   256 threads, 8x8 micro-tile per thread.
// ---------------------------------------------------------------------------
__device__ __forceinline__ void gemm128_body(const float* __restrict__ W,
                                             const float* __restrict__ X,
                                             float*       __restrict__ Y)
{
    __shared__ float As[8][128];
    __shared__ float Bs[8][128];

    const int tid = threadIdx.x;
    const int m0 = blockIdx.y * 128;
    const int n0 = blockIdx.x * 128;
    const int ty = tid >> 4;          // 0..15
    const int tx = tid & 15;          // 0..15

    const int lrow = tid >> 1;        // 0..127 (W tile row)
    const int lc4  = (tid & 1) * 4;   // 0 or 4 (W tile col group)
    const int xk   = tid >> 5;        // 0..7  (X tile row)
    const int xn4  = (tid & 31) * 4;  // X tile col group

    float acc[8][8];
#pragma unroll
    for (int i = 0; i < 8; i++)
#pragma unroll
        for (int j = 0; j < 8; j++) acc[i][j] = 0.f;

    for (int k0 = 0; k0 < 256; k0 += 8) {
        float4 w4 = *(const float4*)(W + (m0 + lrow) * 256 + k0 + lc4);
        float4 x4 = *(const float4*)(X + (k0 + xk) * 1024 + n0 + xn4);
        As[lc4 + 0][lrow] = w4.x;
        As[lc4 + 1][lrow] = w4.y;
        As[lc4 + 2][lrow] = w4.z;
        As[lc4 + 3][lrow] = w4.w;
        *(float4*)&Bs[xk][xn4] = x4;
        __syncthreads();

#pragma unroll
        for (int k = 0; k < 8; k++) {
            float a[8], b[8];
            *(float4*)(a + 0) = *(const float4*)&As[k][ty * 8 + 0];
            *(float4*)(a + 4) = *(const float4*)&As[k][ty * 8 + 4];
            *(float4*)(b + 0) = *(const float4*)&Bs[k][tx * 8 + 0];
            *(float4*)(b + 4) = *(const float4*)&Bs[k][tx * 8 + 4];
#pragma unroll
            for (int i = 0; i < 8; i++)
#pragma unroll
                for (int j = 0; j < 8; j++)
                    acc[i][j] = fmaf(a[i], b[j], acc[i][j]);
        }
        __syncthreads();
    }

#pragma unroll
    for (int i = 0; i < 8; i++) {
        float* yrow = Y + (m0 + ty * 8 + i) * 1024 + n0 + tx * 8;
        *(float4*)(yrow + 0) = make_float4(acc[i][0], acc[i][1], acc[i][2], acc[i][3]);
        *(float4*)(yrow + 4) = make_float4(acc[i][4], acc[i][5], acc[i][6], acc[i][7]);
    }
}

// QKV projections: grid.z in [0,24): b = z/3, w = z%3 selects (Wq,qp,Q)/(Wk,kp,K)/(Wv,kp,V)
__global__ __launch_bounds__(256) void gemm_qkv(const float* __restrict__ Wq,
                                                const float* __restrict__ Wk,
                                                const float* __restrict__ Wv)
{
    int z = blockIdx.z;
    int b = z / 3, w = z - 3 * b;
    const float* W = (w == 0) ? Wq : (w == 1 ? Wk : Wv);
    const float* X = ((w == 0) ? g_qp : g_kp) + b * PLANE;
    float*       Y = ((w == 0) ? g_Q : (w == 1 ? g_K : g_V)) + b * PLANE;
    gemm128_body(W, X, Y);
}

// Output projection on the SMALL grid (Wo commutes with bilinear upsample)
__global__ __launch_bounds__(256) void gemm_o(const float* __restrict__ Wo)
{
    int b = blockIdx.z;
    gemm128_body(Wo, g_Os + b * PLANE, g_ys + b * PLANE);
}

// ---------------------------------------------------------------------------
// Kernel 3: flash attention. grid = (qtile=8, h=8, b=8), 128 threads.
// One thread per query row; K/V tiles of 128 keys staged in smem.
// ---------------------------------------------------------------------------
__global__ __launch_bounds__(128) void attn_kernel()
{
    __shared__ float Kt[128][33];
    __shared__ float Vt[128][33];

    const int b  = blockIdx.z;
    const int h  = blockIdx.y;
    const int qt = blockIdx.x;
    const int t  = threadIdx.x;
    const int qi = qt * 128 + t;

    const long base = ((long)b * 256 + h * 32) * 1024;   // [32][1024] sub-plane
    const float scale = 0.17677669529663687f;            // 1/sqrt(32)

    float q[HD];
#pragma unroll
    for (int d = 0; d < HD; d++) q[d] = g_Q[base + (long)d * 1024 + qi] * scale;

    float o[HD];
#pragma unroll
    for (int d = 0; d < HD; d++) o[d] = 0.f;
    float m = -INFINITY, l = 0.f;

    for (int j0 = 0; j0 < 1024; j0 += 128) {
        __syncthreads();
        for (int i = t; i < 4096; i += 128) {
            int d = i >> 7, j = i & 127;
            Kt[j][d] = g_K[base + (long)d * 1024 + j0 + j];
            Vt[j][d] = g_V[base + (long)d * 1024 + j0 + j];
        }
        __syncthreads();

        for (int jj = 0; jj < 128; jj += 16) {
            float sc[16];
#pragma unroll
            for (int u = 0; u < 16; u++) {
                float s = 0.f;
#pragma unroll
                for (int d = 0; d < HD; d++) s = fmaf(q[d], Kt[jj + u][d], s);
                sc[u] = s;
            }
            float mt = m;
#pragma unroll
            for (int u = 0; u < 16; u++) mt = fmaxf(mt, sc[u]);
            float alpha = __expf(m - mt);
            m = mt;
            l *= alpha;
#pragma unroll
            for (int d = 0; d < HD; d++) o[d] *= alpha;
#pragma unroll
            for (int u = 0; u < 16; u++) {
                float p = __expf(sc[u] - m);
                l += p;
#pragma unroll
                for (int d = 0; d < HD; d++) o[d] = fmaf(p, Vt[jj + u][d], o[d]);
            }
        }
    }

    float inv = 1.f / l;
#pragma unroll
    for (int d = 0; d < HD; d++)
        g_Os[base + (long)d * 1024 + qi] = o[d] * inv;   // coalesced across threads
}

// ---------------------------------------------------------------------------
// Kernel 5: bilinear 2x upsample (half-pixel) + residual + BatchNorm (eval)
// out = (upsample(y_small) + query) * g[c] + b[c]
// ---------------------------------------------------------------------------
__global__ __launch_bounds__(256) void final_kernel(const float* __restrict__ query,
                                                    const float* __restrict__ gamma,
                                                    const float* __restrict__ beta,
                                                    const float* __restrict__ mean,
                                                    const float* __restrict__ var,
                                                    float* __restrict__ out)
{
    int idx = blockIdx.x * blockDim.x + threadIdx.x;
    if (idx >= Bb * Cc * Hh * Ww) return;
    int x = idx & 63;
    int y = (idx >> 6) & 63;
    int c = (idx >> 12) & 255;
    int bc = idx >> 12;                    // b*256+c

    const float* ys = g_ys + (long)bc * 1024;

    int jy = y >> 1;
    int oy = (y & 1) ? min(jy + 1, 31) : max(jy - 1, 0);
    int jx = x >> 1;
    int ox = (x & 1) ? min(jx + 1, 31) : max(jx - 1, 0);

    float v00 = ys[jy * 32 + jx];
    float v01 = ys[jy * 32 + ox];
    float v10 = ys[oy * 32 + jx];
    float v11 = ys[oy * 32 + ox];
    float v = 0.75f * (0.75f * v00 + 0.25f * v01)
            + 0.25f * (0.75f * v10 + 0.25f * v11);

    float g  = gamma[c] * rsqrtf(var[c] + 1e-5f);
    float bb = beta[c] - mean[c] * g;
    out[idx] = (v + query[idx]) * g + bb;
}

// ---------------------------------------------------------------------------
extern "C" void kernel_launch(void* const* d_in, const int* in_sizes, int n_in,
                              void* d_out, int out_size)
{
    (void)in_sizes; (void)n_in; (void)out_size;
    const float* query = (const float*)d_in[0];
    const float* kv    = (const float*)d_in[1];
    const float* Wq    = (const float*)d_in[2];
    const float* Wk    = (const float*)d_in[3];
    const float* Wv    = (const float*)d_in[4];
    const float* Wo    = (const float*)d_in[5];
    const float* gamma = (const float*)d_in[6];
    const float* beta  = (const float*)d_in[7];
    const float* mean  = (const float*)d_in[8];
    const float* var   = (const float*)d_in[9];
    float* out = (float*)d_out;

    pool_kernel<<<(Bb * PLANE + 255) / 256, 256>>>(query, kv);
    gemm_qkv<<<dim3(8, 2, 24), 256>>>(Wq, Wk, Wv);
    attn_kernel<<<dim3(8, 8, 8), 128>>>();
    gemm_o<<<dim3(8, 2, 8), 256>>>(Wo);
    final_kernel<<<(Bb * Cc * Hh * Ww + 255) / 256, 256>>>(query, gamma, beta, mean, var, out);
}

// round 3
// speedup vs baseline: 2.3276x; 2.3276x over previous
#include <cuda_runtime.h>
#include <math.h>
#include <stdint.h>

// Problem constants (fixed by the dataset)
static constexpr int Bb   = 8;
static constexpr int Cc   = 256;
static constexpr int Sp   = 1024;   // pooled spatial 32*32
static constexpr int PLANE = Cc * Sp;

// Scratch (static device globals; allocation-free per harness rules)
__device__ float g_qp[Bb * PLANE];
__device__ float g_kp[Bb * PLANE];
__device__ float g_Q [Bb * PLANE];
__device__ float g_K [Bb * PLANE];
__device__ float g_V [Bb * PLANE];
__device__ float g_Os[Bb * PLANE];
__device__ float g_ys[Bb * PLANE];

__device__ __forceinline__ uint32_t f2tf(float f) {
    uint32_t u;
    asm("cvt.rna.tf32.f32 %0, %1;" : "=r"(u) : "f"(f));
    return u;
}

__device__ __forceinline__ void mma_tf32(float* d, const uint32_t* a,
                                         uint32_t b0, uint32_t b1) {
    asm volatile(
        "mma.sync.aligned.m16n8k8.row.col.f32.tf32.tf32.f32 "
        "{%0,%1,%2,%3}, {%4,%5,%6,%7}, {%8,%9}, {%0,%1,%2,%3};"
        : "+f"(d[0]), "+f"(d[1]), "+f"(d[2]), "+f"(d[3])
        : "r"(a[0]), "r"(a[1]), "r"(a[2]), "r"(a[3]), "r"(b0), "r"(b1));
}

// ---------------------------------------------------------------------------
// Kernel 1: AvgPool2d(2) for query and kv, layout [b][c][s], s = py*32+px
// ---------------------------------------------------------------------------
__global__ __launch_bounds__(256) void pool_kernel(const float* __restrict__ q,
                                                   const float* __restrict__ kv)
{
    int idx = blockIdx.x * blockDim.x + threadIdx.x;
    if (idx >= Bb * PLANE) return;
    int s  = idx & (Sp - 1);
    int px = s & 31;
    int py = s >> 5;
    int bc = idx >> 10;
    long off = ((long)bc * 64 + 2 * py) * 64 + 2 * px;

    float2 a0 = *(const float2*)(q + off);
    float2 a1 = *(const float2*)(q + off + 64);
    g_qp[idx] = 0.25f * (a0.x + a0.y + a1.x + a1.y);

    float2 b0 = *(const float2*)(kv + off);
    float2 b1 = *(const float2*)(kv + off + 64);
    g_kp[idx] = 0.25f * (b0.x + b0.y + b1.x + b1.y);
}

// ---------------------------------------------------------------------------
// TF32 tensor-core GEMM: Y[256][1024] = W[256][256] @ X[256][1024]
// Block tile 128x128, 8 warps (4m x 2n), warp tile 32x64, mma m16n8k8.
// Operands converted to tf32 at smem-store time.
// Smem k-major, stride 136 words => fragment LDS bank = 8*(t%4)+(t/4): unique.
// ---------------------------------------------------------------------------
__device__ __forceinline__ void gemm_tc_body(const float* __restrict__ W,
                                             const float* __restrict__ X,
                                             float*       __restrict__ Y)
{
    __shared__ uint32_t Ws[32][136];  // [k][m]
    __shared__ uint32_t Xs[32][136];  // [k][n]

    const int tid = threadIdx.x;
    const int w = tid >> 5, t = tid & 31, g = t >> 2, c = t & 3;
    const int m0 = blockIdx.y * 128, n0 = blockIdx.x * 128;
    const int wm = (w >> 1) * 32, wn = (w & 1) * 64;

    float acc[2][8][4];
#pragma unroll
    for (int mi = 0; mi < 2; mi++)
#pragma unroll
        for (int ni = 0; ni < 8; ni++)
#pragma unroll
            for (int r = 0; r < 4; r++) acc[mi][ni][r] = 0.f;

    const int lm = tid & 127;         // W row within tile
    const int lk = (tid >> 7) * 16;   // W col group (0/16)
    const int xk = tid >> 3;          // X row 0..31
    const int xn = (tid & 7) * 16;    // X col group

    for (int k0 = 0; k0 < 256; k0 += 32) {
        __syncthreads();
#pragma unroll
        for (int i = 0; i < 4; i++) {
            float4 v = *(const float4*)(W + (long)(m0 + lm) * 256 + k0 + lk + 4 * i);
            Ws[lk + 4 * i + 0][lm] = f2tf(v.x);
            Ws[lk + 4 * i + 1][lm] = f2tf(v.y);
            Ws[lk + 4 * i + 2][lm] = f2tf(v.z);
            Ws[lk + 4 * i + 3][lm] = f2tf(v.w);
        }
#pragma unroll
        for (int i = 0; i < 4; i++) {
            float4 v = *(const float4*)(X + (long)(k0 + xk) * 1024 + n0 + xn + 4 * i);
            uint4 u = make_uint4(f2tf(v.x), f2tf(v.y), f2tf(v.z), f2tf(v.w));
            *(uint4*)&Xs[xk][xn + 4 * i] = u;
        }
        __syncthreads();

#pragma unroll
        for (int ks = 0; ks < 4; ks++) {
            const int kr = ks * 8;
            uint32_t a[2][4], b[8][2];
#pragma unroll
            for (int mi = 0; mi < 2; mi++) {
                int mb = wm + mi * 16;
                a[mi][0] = Ws[kr + c][mb + g];
                a[mi][1] = Ws[kr + c][mb + g + 8];
                a[mi][2] = Ws[kr + c + 4][mb + g];
                a[mi][3] = Ws[kr + c + 4][mb + g + 8];
            }
#pragma unroll
            for (int ni = 0; ni < 8; ni++) {
                b[ni][0] = Xs[kr + c][wn + ni * 8 + g];
                b[ni][1] = Xs[kr + c + 4][wn + ni * 8 + g];
            }
#pragma unroll
            for (int mi = 0; mi < 2; mi++)
#pragma unroll
                for (int ni = 0; ni < 8; ni++)
                    mma_tf32(acc[mi][ni], a[mi], b[ni][0], b[ni][1]);
        }
    }

#pragma unroll
    for (int mi = 0; mi < 2; mi++) {
        int r = m0 + wm + mi * 16 + g;
#pragma unroll
        for (int ni = 0; ni < 8; ni++) {
            int col = n0 + wn + ni * 8 + 2 * c;
            *(float2*)(Y + (long)r * 1024 + col) =
                make_float2(acc[mi][ni][0], acc[mi][ni][1]);
            *(float2*)(Y + (long)(r + 8) * 1024 + col) =
                make_float2(acc[mi][ni][2], acc[mi][ni][3]);
        }
    }
}

__global__ __launch_bounds__(256, 2) void gemm_qkv(const float* __restrict__ Wq,
                                                   const float* __restrict__ Wk,
                                                   const float* __restrict__ Wv)
{
    int z = blockIdx.z;
    int b = z / 3, w = z - 3 * b;
    const float* W = (w == 0) ? Wq : (w == 1 ? Wk : Wv);
    const float* X = ((w == 0) ? g_qp : g_kp) + b * PLANE;
    float*       Y = ((w == 0) ? g_Q : (w == 1 ? g_K : g_V)) + b * PLANE;
    gemm_tc_body(W, X, Y);
}

__global__ __launch_bounds__(256, 2) void gemm_o(const float* __restrict__ Wo)
{
    int b = blockIdx.z;
    gemm_tc_body(Wo, g_Os + b * PLANE, g_ys + b * PLANE);
}

// ---------------------------------------------------------------------------
// Flash attention with tf32 mma. Block = 128 queries x (b,h); 8 warps,
// each warp owns 16 queries (one m16 tile). Keys chunked by 64.
// g_Q/g_K/g_V are [d][s] (d-major) => directly k-major for the S mma.
// ---------------------------------------------------------------------------
__global__ __launch_bounds__(256, 1) void attn_kernel()
{
    __shared__ uint32_t Ks[32][72];      // [d][key]  72 % 32 == 8 -> frag-LDS unique banks
    __shared__ uint32_t Vs[32][68];      // [d][key]  68 % 32 == 4
    __shared__ uint32_t Ps[8][16][36];   // per-warp P  36 % 32 == 4

    const int b  = blockIdx.z;
    const int h  = blockIdx.y;
    const int qt = blockIdx.x;
    const int tid = threadIdx.x;
    const int w = tid >> 5, t = tid & 31, g = t >> 2, c = t & 3;
    const long base = ((long)(b * 256 + h * 32)) * 1024;
    const int q0 = qt * 128 + w * 16;
    const float scale = 0.17677669529663687f;  // 1/sqrt(32)

    // Q fragments (persistent): qa[kstep][4], scale folded in
    uint32_t qa[4][4];
#pragma unroll
    for (int ks = 0; ks < 4; ks++) {
        int d0 = ks * 8;
        qa[ks][0] = f2tf(g_Q[base + (long)(d0 + c) * 1024 + q0 + g] * scale);
        qa[ks][1] = f2tf(g_Q[base + (long)(d0 + c) * 1024 + q0 + g + 8] * scale);
        qa[ks][2] = f2tf(g_Q[base + (long)(d0 + c + 4) * 1024 + q0 + g] * scale);
        qa[ks][3] = f2tf(g_Q[base + (long)(d0 + c + 4) * 1024 + q0 + g + 8] * scale);
    }

    float m0 = -INFINITY, m1 = -INFINITY, l0 = 0.f, l1 = 0.f;
    float o[4][4];
#pragma unroll
    for (int ni = 0; ni < 4; ni++)
#pragma unroll
        for (int r = 0; r < 4; r++) o[ni][r] = 0.f;

    const int dd = tid >> 3;            // staging: d row 0..31
    const int kb = (tid & 7) * 8;       // staging: key group

    for (int k0 = 0; k0 < 1024; k0 += 64) {
        __syncthreads();
        // stage K,V (64 keys x 32 d), tf32-converted, uint4 stores
#pragma unroll
        for (int i = 0; i < 2; i++) {
            float4 v = *(const float4*)(g_K + base + (long)dd * 1024 + k0 + kb + 4 * i);
            *(uint4*)&Ks[dd][kb + 4 * i] =
                make_uint4(f2tf(v.x), f2tf(v.y), f2tf(v.z), f2tf(v.w));
            float4 u = *(const float4*)(g_V + base + (long)dd * 1024 + k0 + kb + 4 * i);
            *(uint4*)&Vs[dd][kb + 4 * i] =
                make_uint4(f2tf(u.x), f2tf(u.y), f2tf(u.z), f2tf(u.w));
        }
        __syncthreads();

        // S = Q K^T over 64 keys: 8 ntiles
        float S[8][4];
#pragma unroll
        for (int ni = 0; ni < 8; ni++)
#pragma unroll
            for (int r = 0; r < 4; r++) S[ni][r] = 0.f;
#pragma unroll
        for (int ks = 0; ks < 4; ks++) {
            const int kr = ks * 8;
#pragma unroll
            for (int ni = 0; ni < 8; ni++) {
                uint32_t b0 = Ks[kr + c][ni * 8 + g];
                uint32_t b1 = Ks[kr + c + 4][ni * 8 + g];
                mma_tf32(S[ni], qa[ks], b0, b1);
            }
        }

        // online softmax (rows r0 = g, r1 = g+8); quad lanes share a row
        float mx0 = m0, mx1 = m1;
#pragma unroll
        for (int ni = 0; ni < 8; ni++) {
            mx0 = fmaxf(mx0, fmaxf(S[ni][0], S[ni][1]));
            mx1 = fmaxf(mx1, fmaxf(S[ni][2], S[ni][3]));
        }
        mx0 = fmaxf(mx0, __shfl_xor_sync(0xffffffffu, mx0, 1));
        mx0 = fmaxf(mx0, __shfl_xor_sync(0xffffffffu, mx0, 2));
        mx1 = fmaxf(mx1, __shfl_xor_sync(0xffffffffu, mx1, 1));
        mx1 = fmaxf(mx1, __shfl_xor_sync(0xffffffffu, mx1, 2));
        float a0 = __expf(m0 - mx0);
        float a1 = __expf(m1 - mx1);
        m0 = mx0; m1 = mx1;
        float s0 = 0.f, s1 = 0.f;
#pragma unroll
        for (int ni = 0; ni < 8; ni++) {
            S[ni][0] = __expf(S[ni][0] - m0); s0 += S[ni][0];
            S[ni][1] = __expf(S[ni][1] - m0); s0 += S[ni][1];
            S[ni][2] = __expf(S[ni][2] - m1); s1 += S[ni][2];
            S[ni][3] = __expf(S[ni][3] - m1); s1 += S[ni][3];
        }
        s0 += __shfl_xor_sync(0xffffffffu, s0, 1);
        s0 += __shfl_xor_sync(0xffffffffu, s0, 2);
        s1 += __shfl_xor_sync(0xffffffffu, s1, 1);
        s1 += __shfl_xor_sync(0xffffffffu, s1, 2);
        l0 = l0 * a0 + s0;
        l1 = l1 * a1 + s1;
#pragma unroll
        for (int ni = 0; ni < 4; ni++) {
            o[ni][0] *= a0; o[ni][1] *= a0;
            o[ni][2] *= a1; o[ni][3] *= a1;
        }

        // P·V in 2 pieces of 32 keys (P transposed through per-warp smem)
#pragma unroll
        for (int piece = 0; piece < 2; piece++) {
#pragma unroll
            for (int j = 0; j < 4; j++) {
                int ni = piece * 4 + j;
                Ps[w][g][j * 8 + 2 * c]     = f2tf(S[ni][0]);
                Ps[w][g][j * 8 + 2 * c + 1] = f2tf(S[ni][1]);
                Ps[w][g + 8][j * 8 + 2 * c]     = f2tf(S[ni][2]);
                Ps[w][g + 8][j * 8 + 2 * c + 1] = f2tf(S[ni][3]);
            }
            __syncwarp();
#pragma unroll
            for (int ks = 0; ks < 4; ks++) {
                uint32_t pa[4];
                pa[0] = Ps[w][g][ks * 8 + c];
                pa[1] = Ps[w][g + 8][ks * 8 + c];
                pa[2] = Ps[w][g][ks * 8 + c + 4];
                pa[3] = Ps[w][g + 8][ks * 8 + c + 4];
                int key = piece * 32 + ks * 8;
#pragma unroll
                for (int ni = 0; ni < 4; ni++) {
                    uint32_t b0 = Vs[ni * 8 + g][key + c];
                    uint32_t b1 = Vs[ni * 8 + g][key + c + 4];
                    mma_tf32(o[ni], pa, b0, b1);
                }
            }
            __syncwarp();
        }
    }

    // normalize and write to g_Os [d][q]
    float inv0 = 1.f / l0, inv1 = 1.f / l1;
#pragma unroll
    for (int ni = 0; ni < 4; ni++) {
        int d = ni * 8 + 2 * c;
        int q = q0 + g;
        g_Os[base + (long)d * 1024 + q]           = o[ni][0] * inv0;
        g_Os[base + (long)(d + 1) * 1024 + q]     = o[ni][1] * inv0;
        g_Os[base + (long)d * 1024 + q + 8]       = o[ni][2] * inv1;
        g_Os[base + (long)(d + 1) * 1024 + q + 8] = o[ni][3] * inv1;
    }
}

// ---------------------------------------------------------------------------
// Kernel 5: bilinear 2x upsample (half-pixel) + residual + BatchNorm (eval)
// ---------------------------------------------------------------------------
__global__ __launch_bounds__(256) void final_kernel(const float* __restrict__ query,
                                                    const float* __restrict__ gamma,
                                                    const float* __restrict__ beta,
                                                    const float* __restrict__ mean,
                                                    const float* __restrict__ var,
                                                    float* __restrict__ out)
{
    int idx = blockIdx.x * blockDim.x + threadIdx.x;
    if (idx >= Bb * Cc * 64 * 64) return;
    int x = idx & 63;
    int y = (idx >> 6) & 63;
    int c = (idx >> 12) & 255;
    int bc = idx >> 12;

    const float* ys = g_ys + (long)bc * 1024;

    int jy = y >> 1;
    int oy = (y & 1) ? min(jy + 1, 31) : max(jy - 1, 0);
    int jx = x >> 1;
    int ox = (x & 1) ? min(jx + 1, 31) : max(jx - 1, 0);

    float v00 = ys[jy * 32 + jx];
    float v01 = ys[jy * 32 + ox];
    float v10 = ys[oy * 32 + jx];
    float v11 = ys[oy * 32 + ox];
    float v = 0.75f * (0.75f * v00 + 0.25f * v01)
            + 0.25f * (0.75f * v10 + 0.25f * v11);

    float gg = gamma[c] * rsqrtf(var[c] + 1e-5f);
    float bb = beta[c] - mean[c] * gg;
    out[idx] = (v + query[idx]) * gg + bb;
}

// ---------------------------------------------------------------------------
extern "C" void kernel_launch(void* const* d_in, const int* in_sizes, int n_in,
                              void* d_out, int out_size)
{
    (void)in_sizes; (void)n_in; (void)out_size;
    const float* query = (const float*)d_in[0];
    const float* kv    = (const float*)d_in[1];
    const float* Wq    = (const float*)d_in[2];
    const float* Wk    = (const float*)d_in[3];
    const float* Wv    = (const float*)d_in[4];
    const float* Wo    = (const float*)d_in[5];
    const float* gamma = (const float*)d_in[6];
    const float* beta  = (const float*)d_in[7];
    const float* mean  = (const float*)d_in[8];
    const float* var   = (const float*)d_in[9];
    float* out = (float*)d_out;

    pool_kernel<<<(Bb * PLANE + 255) / 256, 256>>>(query, kv);
    gemm_qkv<<<dim3(8, 2, 24), 256>>>(Wq, Wk, Wv);
    attn_kernel<<<dim3(8, 8, 8), 256>>>();
    gemm_o<<<dim3(8, 2, 8), 256>>>(Wo);
    final_kernel<<<(Bb * Cc * 64 * 64 + 255) / 256, 256>>>(query, gamma, beta, mean, var, out);
}

// round 4
// speedup vs baseline: 4.4658x; 1.9186x over previous
#include <cuda_runtime.h>
#include <math.h>
#include <stdint.h>

static constexpr int Bb    = 8;
static constexpr int PLANE = 256 * 1024;

// Scratch (static device globals; allocation-free per harness rules)
// packed bf16x2 activations: [b][c2=128][s=1024] (pairs along channel)
__device__ uint32_t g_qp [8 * 128 * 1024];
__device__ uint32_t g_kpx[8 * 128 * 1024];
__device__ uint32_t g_Qp [8 * 128 * 1024];
__device__ uint32_t g_Kp [8 * 128 * 1024];
__device__ uint32_t g_Vp [8 * 256 * 512];   // [b][d=256][s2=512] (pairs along s)
__device__ uint32_t g_Osp[8 * 128 * 1024];  // attention out, packed like g_qp
__device__ float    g_ys [8 * 256 * 1024];  // Wo output (small grid), fp32
__device__ uint32_t g_Wk [4 * 128 * 256];   // weights k-major packed: [w][c2][o]

// ---------------------------------------------------------------------------
__device__ __forceinline__ uint32_t pk(float lo, float hi) {
    uint32_t r;
    asm("cvt.rn.bf16x2.f32 %0, %1, %2;" : "=r"(r) : "f"(hi), "f"(lo));
    return r;
}
__device__ __forceinline__ void mma_bf16(float* d, const uint32_t* a,
                                         uint32_t b0, uint32_t b1) {
    asm volatile(
        "mma.sync.aligned.m16n8k16.row.col.f32.bf16.bf16.f32 "
        "{%0,%1,%2,%3}, {%4,%5,%6,%7}, {%8,%9}, {%0,%1,%2,%3};"
        : "+f"(d[0]), "+f"(d[1]), "+f"(d[2]), "+f"(d[3])
        : "r"(a[0]), "r"(a[1]), "r"(a[2]), "r"(a[3]), "r"(b0), "r"(b1));
}
__device__ __forceinline__ void cpa16(uint32_t dst, const void* src) {
    asm volatile("cp.async.cg.shared.global [%0], [%1], 16;" :: "r"(dst), "l"(src));
}
__device__ __forceinline__ void cp_commit() { asm volatile("cp.async.commit_group;"); }
__device__ __forceinline__ void cp_wait1()  { asm volatile("cp.async.wait_group 1;"); }
__device__ __forceinline__ void cp_wait0()  { asm volatile("cp.async.wait_group 0;"); }
__device__ __forceinline__ float ex2(float x) {
    float y; asm("ex2.approx.f32 %0, %1;" : "=f"(y) : "f"(x)); return y;
}
__device__ __forceinline__ uint32_t smem_u32(const void* p) {
    return (uint32_t)__cvta_generic_to_shared(p);
}

// ---------------------------------------------------------------------------
// Prep: weights -> k-major packed bf16x2.  Wq gets scale*log2(e) folded in.
// ---------------------------------------------------------------------------
__global__ __launch_bounds__(256) void prep_w(const float* __restrict__ Wq,
                                              const float* __restrict__ Wk_,
                                              const float* __restrict__ Wv,
                                              const float* __restrict__ Wo)
{
    int idx = blockIdx.x * 256 + threadIdx.x;   // 131072 total
    int w  = idx >> 15;
    int c2 = (idx >> 8) & 127;
    int o  = idx & 255;
    const float* W = (w == 0) ? Wq : (w == 1) ? Wk_ : (w == 2) ? Wv : Wo;
    float2 v = *(const float2*)(W + o * 256 + 2 * c2);
    if (w == 0) {
        const float qs = 0.17677669529663687f * 1.4426950408889634f; // /sqrt(32)*log2e
        v.x *= qs; v.y *= qs;
    }
    g_Wk[(w * 128 + c2) * 256 + o] = pk(v.x, v.y);
}

// ---------------------------------------------------------------------------
// Pool: AvgPool2d(2) -> packed bf16x2 [c2][s] for query and kv.
// Thread handles (b, c2, 4 pooled pixels).
// ---------------------------------------------------------------------------
__global__ __launch_bounds__(256) void pool_kernel(const float* __restrict__ q,
                                                   const float* __restrict__ kv)
{
    int idx = blockIdx.x * 256 + threadIdx.x;   // 262144 total
    int s4 = idx & 255;
    int c2 = (idx >> 8) & 127;
    int b  = idx >> 15;
    int s  = s4 << 2;
    int px = s & 31, py = s >> 5;

    long base0 = (((long)(b * 256 + 2 * c2)) * 64 + 2 * py) * 64 + 2 * px;
    long base1 = base0 + 4096;  // next channel

    uint32_t outq[4], outk[4];
#pragma unroll
    for (int tsel = 0; tsel < 2; tsel++) {
        const float* src = tsel ? kv : q;
        float4 a00 = *(const float4*)(src + base0);
        float4 a01 = *(const float4*)(src + base0 + 4);
        float4 a10 = *(const float4*)(src + base0 + 64);
        float4 a11 = *(const float4*)(src + base0 + 68);
        float4 b00 = *(const float4*)(src + base1);
        float4 b01 = *(const float4*)(src + base1 + 4);
        float4 b10 = *(const float4*)(src + base1 + 64);
        float4 b11 = *(const float4*)(src + base1 + 68);
        float pA0 = 0.25f * (a00.x + a00.y + a10.x + a10.y);
        float pA1 = 0.25f * (a00.z + a00.w + a10.z + a10.w);
        float pA2 = 0.25f * (a01.x + a01.y + a11.x + a11.y);
        float pA3 = 0.25f * (a01.z + a01.w + a11.z + a11.w);
        float pB0 = 0.25f * (b00.x + b00.y + b10.x + b10.y);
        float pB1 = 0.25f * (b00.z + b00.w + b10.z + b10.w);
        float pB2 = 0.25f * (b01.x + b01.y + b11.x + b11.y);
        float pB3 = 0.25f * (b01.z + b01.w + b11.z + b11.w);
        uint32_t* dst = tsel ? outk : outq;
        dst[0] = pk(pA0, pB0); dst[1] = pk(pA1, pB1);
        dst[2] = pk(pA2, pB2); dst[3] = pk(pA3, pB3);
    }
    long off = ((long)(b * 128 + c2) << 10) + s;
    *(uint4*)&g_qp [off] = make_uint4(outq[0], outq[1], outq[2], outq[3]);
    *(uint4*)&g_kpx[off] = make_uint4(outk[0], outk[1], outk[2], outk[3]);
}

// ---------------------------------------------------------------------------
// bf16 GEMM body: Y[256][1024] = W @ X, block 128x128, 2-stage cp.async.
// Wk: [c2=128][o=256] packed; X: [c2=128][s=1024] packed.
// smem k-major (16 packed rows per 32-k block), stride 136 -> conflict-free.
// ---------------------------------------------------------------------------
__device__ __forceinline__ void gemm_body(const uint32_t* __restrict__ Wk,
                                          const uint32_t* __restrict__ X,
                                          uint32_t Ws[2][16][136],
                                          uint32_t Xs[2][16][136],
                                          float acc[2][8][4],
                                          int m0, int n0)
{
    const int tid = threadIdx.x;
    const int w = tid >> 5, t = tid & 31, g = t >> 2, c = t & 3;
    const int wm = (w >> 1) * 32, wn = (w & 1) * 64;

#pragma unroll
    for (int mi = 0; mi < 2; mi++)
#pragma unroll
        for (int ni = 0; ni < 8; ni++)
#pragma unroll
            for (int r = 0; r < 4; r++) acc[mi][ni][r] = 0.f;

    const int sr = tid >> 5;            // not used for staging; see below
    (void)sr;

    // stage(s, kb): 256 threads x (2 W-chunks + 2 X-chunks) of 16B
    auto stage = [&](int s, int kb) {
        uint32_t wb = smem_u32(&Ws[s][0][0]);
        uint32_t xb = smem_u32(&Xs[s][0][0]);
#pragma unroll
        for (int i = 0; i < 2; i++) {
            int id = tid + (i << 8);
            int r = id >> 5, col = (id & 31) << 2;
            cpa16(wb + (uint32_t)((r * 136 + col) << 2),
                  Wk + (kb * 16 + r) * 256 + m0 + col);
            cpa16(xb + (uint32_t)((r * 136 + col) << 2),
                  X + (kb * 16 + r) * 1024 + n0 + col);
        }
        cp_commit();
    };

    stage(0, 0);
    for (int kb = 0; kb < 8; kb++) {
        int cur = kb & 1;
        if (kb < 7) { stage(1 - cur, kb + 1); cp_wait1(); }
        else        { cp_wait0(); }
        __syncthreads();
#pragma unroll
        for (int ks = 0; ks < 2; ks++) {
            uint32_t a[2][4];
#pragma unroll
            for (int mi = 0; mi < 2; mi++) {
                int mb = wm + mi * 16;
                a[mi][0] = Ws[cur][8 * ks + c][mb + g];
                a[mi][1] = Ws[cur][8 * ks + c][mb + g + 8];
                a[mi][2] = Ws[cur][8 * ks + c + 4][mb + g];
                a[mi][3] = Ws[cur][8 * ks + c + 4][mb + g + 8];
            }
#pragma unroll
            for (int ni = 0; ni < 8; ni++) {
                uint32_t b0 = Xs[cur][8 * ks + c][wn + ni * 8 + g];
                uint32_t b1 = Xs[cur][8 * ks + c + 4][wn + ni * 8 + g];
                mma_bf16(acc[0][ni], a[0], b0, b1);
                mma_bf16(acc[1][ni], a[1], b0, b1);
            }
        }
        __syncthreads();
    }
}

// QKV: w3=0 -> Q (shfl-pack [d2][s]); 1 -> K (same); 2 -> V (pack [d][s2])
__global__ __launch_bounds__(256, 2) void gemm_qkv()
{
    __shared__ uint32_t Ws[2][16][136];
    __shared__ uint32_t Xs[2][16][136];
    int z = blockIdx.z;
    int b = z / 3, w3 = z - 3 * b;
    const uint32_t* Wk = g_Wk + w3 * 128 * 256;
    const uint32_t* X  = ((w3 == 0) ? g_qp : g_kpx) + b * 128 * 1024;
    int m0 = blockIdx.y * 128, n0 = blockIdx.x * 128;

    float acc[2][8][4];
    gemm_body(Wk, X, Ws, Xs, acc, m0, n0);

    const int tid = threadIdx.x;
    const int w = tid >> 5, t = tid & 31, g = t >> 2, c = t & 3;
    const int wm = (w >> 1) * 32, wn = (w & 1) * 64;

    if (w3 < 2) {
        uint32_t* Yp = ((w3 == 0) ? g_Qp : g_Kp) + b * 128 * 1024;
        bool even = (g & 1) == 0;
#pragma unroll
        for (int mi = 0; mi < 2; mi++) {
            int base = m0 + wm + mi * 16;
#pragma unroll
            for (int ni = 0; ni < 8; ni++) {
                float p0 = __shfl_xor_sync(0xffffffffu, acc[mi][ni][0], 4);
                float p1 = __shfl_xor_sync(0xffffffffu, acc[mi][ni][1], 4);
                float p2 = __shfl_xor_sync(0xffffffffu, acc[mi][ni][2], 4);
                float p3 = __shfl_xor_sync(0xffffffffu, acc[mi][ni][3], 4);
                uint32_t w0, w1; int d2;
                if (even) {
                    w0 = pk(acc[mi][ni][0], p0);
                    w1 = pk(acc[mi][ni][1], p1);
                    d2 = (base + g) >> 1;
                } else {
                    w0 = pk(p2, acc[mi][ni][2]);
                    w1 = pk(p3, acc[mi][ni][3]);
                    d2 = (base + 7 + g) >> 1;
                }
                int col = n0 + wn + ni * 8 + 2 * c;
                *(uint2*)&Yp[(long)d2 * 1024 + col] = make_uint2(w0, w1);
            }
        }
    } else {
        uint32_t* Vp = g_Vp + b * 256 * 512;
#pragma unroll
        for (int mi = 0; mi < 2; mi++) {
            int base = m0 + wm + mi * 16;
#pragma unroll
            for (int ni = 0; ni < 8; ni++) {
                int s2 = ((n0 + wn) >> 1) + ni * 4 + c;
                Vp[(long)(base + g) * 512 + s2]     = pk(acc[mi][ni][0], acc[mi][ni][1]);
                Vp[(long)(base + g + 8) * 512 + s2] = pk(acc[mi][ni][2], acc[mi][ni][3]);
            }
        }
    }
}

__global__ __launch_bounds__(256, 2) void gemm_o()
{
    __shared__ uint32_t Ws[2][16][136];
    __shared__ uint32_t Xs[2][16][136];
    int b = blockIdx.z;
    int m0 = blockIdx.y * 128, n0 = blockIdx.x * 128;
    float acc[2][8][4];
    gemm_body(g_Wk + 3 * 128 * 256, g_Osp + b * 128 * 1024, Ws, Xs, acc, m0, n0);

    const int tid = threadIdx.x;
    const int w = tid >> 5, t = tid & 31, g = t >> 2, c = t & 3;
    const int wm = (w >> 1) * 32, wn = (w & 1) * 64;
    float* Y = g_ys + (long)b * PLANE;
#pragma unroll
    for (int mi = 0; mi < 2; mi++) {
        int r = m0 + wm + mi * 16 + g;
#pragma unroll
        for (int ni = 0; ni < 8; ni++) {
            int col = n0 + wn + ni * 8 + 2 * c;
            *(float2*)(Y + (long)r * 1024 + col) =
                make_float2(acc[mi][ni][0], acc[mi][ni][1]);
            *(float2*)(Y + (long)(r + 8) * 1024 + col) =
                make_float2(acc[mi][ni][2], acc[mi][ni][3]);
        }
    }
}

// ---------------------------------------------------------------------------
// Flash attention, bf16 mma, 2-stage cp.async, register-resident P.
// Block = 128 queries x (b,h); warp owns 16 queries. 64-key tiles.
// ---------------------------------------------------------------------------
__global__ __launch_bounds__(256, 2) void attn_kernel()
{
    __shared__ uint32_t Ks[2][16][72];   // [d2][key]
    __shared__ uint32_t Vs[2][32][36];   // [d][s2]

    const int b  = blockIdx.z;
    const int h  = blockIdx.y;
    const int qt = blockIdx.x;
    const int tid = threadIdx.x;
    const int w = tid >> 5, t = tid & 31, g = t >> 2, c = t & 3;
    const int q0 = qt * 128 + w * 16;

    const uint32_t* Qp = g_Qp + (long)(b * 128 + h * 16) * 1024;
    const uint32_t* Kp = g_Kp + (long)(b * 128 + h * 16) * 1024;
    const uint32_t* Vp = g_Vp + (long)(b * 256 + h * 32) * 512;

    // Q fragments (scale*log2e folded into Wq)
    uint32_t qa[2][4];
#pragma unroll
    for (int ks = 0; ks < 2; ks++) {
        qa[ks][0] = Qp[(8 * ks + c) * 1024 + q0 + g];
        qa[ks][1] = Qp[(8 * ks + c) * 1024 + q0 + g + 8];
        qa[ks][2] = Qp[(8 * ks + c + 4) * 1024 + q0 + g];
        qa[ks][3] = Qp[(8 * ks + c + 4) * 1024 + q0 + g + 8];
    }

    float m0v = -INFINITY, m1v = -INFINITY, l0 = 0.f, l1 = 0.f;
    float o[4][4];
#pragma unroll
    for (int ni = 0; ni < 4; ni++)
#pragma unroll
        for (int r = 0; r < 4; r++) o[ni][r] = 0.f;

    const int kr = tid >> 4, kc = (tid & 15) << 2;   // K chunk: 16 rows x 64 words
    const int vr = tid >> 3, vc = (tid & 7) << 2;    // V chunk: 32 rows x 32 words

    auto stage = [&](int s, int k0) {
        cpa16(smem_u32(&Ks[s][0][0]) + (uint32_t)((kr * 72 + kc) << 2),
              Kp + kr * 1024 + k0 + kc);
        cpa16(smem_u32(&Vs[s][0][0]) + (uint32_t)((vr * 36 + vc) << 2),
              Vp + vr * 512 + (k0 >> 1) + vc);
        cp_commit();
    };

    stage(0, 0);
    for (int it = 0; it < 16; it++) {
        int cur = it & 1;
        if (it < 15) { stage(1 - cur, (it + 1) * 64); cp_wait1(); }
        else         { cp_wait0(); }
        __syncthreads();

        // S = Q K^T (base-2 logits)
        float S[8][4];
#pragma unroll
        for (int ni = 0; ni < 8; ni++)
#pragma unroll
            for (int r = 0; r < 4; r++) S[ni][r] = 0.f;
#pragma unroll
        for (int ks = 0; ks < 2; ks++) {
#pragma unroll
            for (int ni = 0; ni < 8; ni++) {
                uint32_t b0 = Ks[cur][8 * ks + c][ni * 8 + g];
                uint32_t b1 = Ks[cur][8 * ks + c + 4][ni * 8 + g];
                mma_bf16(S[ni], qa[ks], b0, b1);
            }
        }

        // online softmax (base-2)
        float mx0 = m0v, mx1 = m1v;
#pragma unroll
        for (int ni = 0; ni < 8; ni++) {
            mx0 = fmaxf(mx0, fmaxf(S[ni][0], S[ni][1]));
            mx1 = fmaxf(mx1, fmaxf(S[ni][2], S[ni][3]));
        }
        mx0 = fmaxf(mx0, __shfl_xor_sync(0xffffffffu, mx0, 1));
        mx0 = fmaxf(mx0, __shfl_xor_sync(0xffffffffu, mx0, 2));
        mx1 = fmaxf(mx1, __shfl_xor_sync(0xffffffffu, mx1, 1));
        mx1 = fmaxf(mx1, __shfl_xor_sync(0xffffffffu, mx1, 2));
        float a0 = ex2(m0v - mx0);
        float a1 = ex2(m1v - mx1);
        m0v = mx0; m1v = mx1;
        float s0 = 0.f, s1 = 0.f;
#pragma unroll
        for (int ni = 0; ni < 8; ni++) {
            S[ni][0] = ex2(S[ni][0] - mx0); s0 += S[ni][0];
            S[ni][1] = ex2(S[ni][1] - mx0); s0 += S[ni][1];
            S[ni][2] = ex2(S[ni][2] - mx1); s1 += S[ni][2];
            S[ni][3] = ex2(S[ni][3] - mx1); s1 += S[ni][3];
        }
        s0 += __shfl_xor_sync(0xffffffffu, s0, 1);
        s0 += __shfl_xor_sync(0xffffffffu, s0, 2);
        s1 += __shfl_xor_sync(0xffffffffu, s1, 1);
        s1 += __shfl_xor_sync(0xffffffffu, s1, 2);
        l0 = l0 * a0 + s0;
        l1 = l1 * a1 + s1;
#pragma unroll
        for (int ni = 0; ni < 4; ni++) {
            o[ni][0] *= a0; o[ni][1] *= a0;
            o[ni][2] *= a1; o[ni][3] *= a1;
        }

        // P·V — P A-fragments come straight from S registers (bf16 pack)
#pragma unroll
        for (int ks4 = 0; ks4 < 4; ks4++) {
            uint32_t pa[4];
            pa[0] = pk(S[2 * ks4][0],     S[2 * ks4][1]);
            pa[1] = pk(S[2 * ks4][2],     S[2 * ks4][3]);
            pa[2] = pk(S[2 * ks4 + 1][0], S[2 * ks4 + 1][1]);
            pa[3] = pk(S[2 * ks4 + 1][2], S[2 * ks4 + 1][3]);
#pragma unroll
            for (int ni = 0; ni < 4; ni++) {
                uint32_t b0 = Vs[cur][ni * 8 + g][8 * ks4 + c];
                uint32_t b1 = Vs[cur][ni * 8 + g][8 * ks4 + c + 4];
                mma_bf16(o[ni], pa, b0, b1);
            }
        }
        __syncthreads();
    }

    // normalize, pack along d, write g_Osp [d2][q]
    float inv0 = 1.f / l0, inv1 = 1.f / l1;
    uint32_t* Osp = g_Osp + (long)(b * 128 + h * 16) * 1024;
#pragma unroll
    for (int ni = 0; ni < 4; ni++) {
        int d2 = 4 * ni + c;
        Osp[(long)d2 * 1024 + q0 + g]     = pk(o[ni][0] * inv0, o[ni][1] * inv0);
        Osp[(long)d2 * 1024 + q0 + g + 8] = pk(o[ni][2] * inv1, o[ni][3] * inv1);
    }
}

// ---------------------------------------------------------------------------
// Final: bilinear 2x upsample + residual + BatchNorm(eval)
// ---------------------------------------------------------------------------
__global__ __launch_bounds__(256) void final_kernel(const float* __restrict__ query,
                                                    const float* __restrict__ gamma,
                                                    const float* __restrict__ beta,
                                                    const float* __restrict__ mean,
                                                    const float* __restrict__ var,
                                                    float* __restrict__ out)
{
    int idx = blockIdx.x * blockDim.x + threadIdx.x;
    if (idx >= Bb * 256 * 64 * 64) return;
    int x = idx & 63;
    int y = (idx >> 6) & 63;
    int c = (idx >> 12) & 255;
    int bc = idx >> 12;

    const float* ys = g_ys + (long)bc * 1024;

    int jy = y >> 1;
    int oy = (y & 1) ? min(jy + 1, 31) : max(jy - 1, 0);
    int jx = x >> 1;
    int ox = (x & 1) ? min(jx + 1, 31) : max(jx - 1, 0);

    float v00 = ys[jy * 32 + jx];
    float v01 = ys[jy * 32 + ox];
    float v10 = ys[oy * 32 + jx];
    float v11 = ys[oy * 32 + ox];
    float v = 0.75f * (0.75f * v00 + 0.25f * v01)
            + 0.25f * (0.75f * v10 + 0.25f * v11);

    float gg = gamma[c] * rsqrtf(var[c] + 1e-5f);
    float bb = beta[c] - mean[c] * gg;
    out[idx] = (v + query[idx]) * gg + bb;
}

// ---------------------------------------------------------------------------
extern "C" void kernel_launch(void* const* d_in, const int* in_sizes, int n_in,
                              void* d_out, int out_size)
{
    (void)in_sizes; (void)n_in; (void)out_size;
    const float* query = (const float*)d_in[0];
    const float* kv    = (const float*)d_in[1];
    const float* Wq    = (const float*)d_in[2];
    const float* Wk    = (const float*)d_in[3];
    const float* Wv    = (const float*)d_in[4];
    const float* Wo    = (const float*)d_in[5];
    const float* gamma = (const float*)d_in[6];
    const float* beta  = (const float*)d_in[7];
    const float* mean  = (const float*)d_in[8];
    const float* var   = (const float*)d_in[9];
    float* out = (float*)d_out;

    prep_w<<<512, 256>>>(Wq, Wk, Wv, Wo);
    pool_kernel<<<1024, 256>>>(query, kv);
    gemm_qkv<<<dim3(8, 2, 24), 256>>>();
    attn_kernel<<<dim3(8, 8, 8), 256>>>();
    gemm_o<<<dim3(8, 2, 8), 256>>>();
    final_kernel<<<(Bb * 256 * 64 * 64 + 255) / 256, 256>>>(query, gamma, beta, mean, var, out);
}

// round 5
// speedup vs baseline: 4.9811x; 1.1154x over previous
#include <cuda_runtime.h>
#include <math.h>
#include <stdint.h>

static constexpr int Bb    = 8;
static constexpr int PLANE = 256 * 1024;

// Scratch (static device globals; allocation-free per harness rules)
// packed bf16x2 activations (pairs along channel unless noted)
__device__ uint32_t g_qp [8 * 128 * 1024];  // [b][c2][s]
__device__ uint32_t g_kpx[8 * 128 * 1024];  // [b][c2][s]
__device__ uint32_t g_Qp [8 * 128 * 1024];  // [b][c2][s]
__device__ uint32_t g_Kp [8 * 1024 * 128];  // [b][s][c2]  (LDSM-friendly)
__device__ uint32_t g_Vp [8 * 256 * 512];   // [b][d][s2]  (pairs along s)
__device__ uint32_t g_Osp[8 * 128 * 1024];  // [b][c2][s]
__device__ float    g_ys [8 * 256 * 1024];  // Wo output (small grid), fp32
__device__ uint32_t g_Wk [4 * 128 * 256];   // weights k-major packed: [w][c2][o]

// ---------------------------------------------------------------------------
__device__ __forceinline__ uint32_t pk(float lo, float hi) {
    uint32_t r;
    asm("cvt.rn.bf16x2.f32 %0, %1, %2;" : "=r"(r) : "f"(hi), "f"(lo));
    return r;
}
__device__ __forceinline__ void mma_bf16(float* d, const uint32_t* a,
                                         uint32_t b0, uint32_t b1) {
    asm volatile(
        "mma.sync.aligned.m16n8k16.row.col.f32.bf16.bf16.f32 "
        "{%0,%1,%2,%3}, {%4,%5,%6,%7}, {%8,%9}, {%0,%1,%2,%3};"
        : "+f"(d[0]), "+f"(d[1]), "+f"(d[2]), "+f"(d[3])
        : "r"(a[0]), "r"(a[1]), "r"(a[2]), "r"(a[3]), "r"(b0), "r"(b1));
}
__device__ __forceinline__ void ldsm4(uint32_t& r0, uint32_t& r1,
                                      uint32_t& r2, uint32_t& r3, uint32_t addr) {
    asm volatile("ldmatrix.sync.aligned.m8n8.x4.shared.b16 {%0,%1,%2,%3}, [%4];"
                 : "=r"(r0), "=r"(r1), "=r"(r2), "=r"(r3) : "r"(addr));
}
__device__ __forceinline__ void cpa16(uint32_t dst, const void* src) {
    asm volatile("cp.async.cg.shared.global [%0], [%1], 16;" :: "r"(dst), "l"(src));
}
__device__ __forceinline__ void cp_commit() { asm volatile("cp.async.commit_group;"); }
__device__ __forceinline__ void cp_wait1()  { asm volatile("cp.async.wait_group 1;"); }
__device__ __forceinline__ void cp_wait0()  { asm volatile("cp.async.wait_group 0;"); }
__device__ __forceinline__ float ex2(float x) {
    float y; asm("ex2.approx.f32 %0, %1;" : "=f"(y) : "f"(x)); return y;
}
__device__ __forceinline__ uint32_t smem_u32(const void* p) {
    return (uint32_t)__cvta_generic_to_shared(p);
}

// ---------------------------------------------------------------------------
// Prep: weights -> k-major packed bf16x2.  Wq gets scale*log2(e) folded in.
// ---------------------------------------------------------------------------
__global__ __launch_bounds__(256) void prep_w(const float* __restrict__ Wq,
                                              const float* __restrict__ Wk_,
                                              const float* __restrict__ Wv,
                                              const float* __restrict__ Wo)
{
    int idx = blockIdx.x * 256 + threadIdx.x;   // 131072 total
    int w  = idx >> 15;
    int c2 = (idx >> 8) & 127;
    int o  = idx & 255;
    const float* W = (w == 0) ? Wq : (w == 1) ? Wk_ : (w == 2) ? Wv : Wo;
    float2 v = *(const float2*)(W + o * 256 + 2 * c2);
    if (w == 0) {
        const float qs = 0.17677669529663687f * 1.4426950408889634f; // /sqrt(32)*log2e
        v.x *= qs; v.y *= qs;
    }
    g_Wk[(w * 128 + c2) * 256 + o] = pk(v.x, v.y);
}

// ---------------------------------------------------------------------------
// Pool: AvgPool2d(2) -> packed bf16x2 [c2][s] for query and kv.
// ---------------------------------------------------------------------------
__global__ __launch_bounds__(256) void pool_kernel(const float* __restrict__ q,
                                                   const float* __restrict__ kv)
{
    int idx = blockIdx.x * 256 + threadIdx.x;   // 262144 total
    int s4 = idx & 255;
    int c2 = (idx >> 8) & 127;
    int b  = idx >> 15;
    int s  = s4 << 2;
    int px = s & 31, py = s >> 5;

    long base0 = (((long)(b * 256 + 2 * c2)) * 64 + 2 * py) * 64 + 2 * px;
    long base1 = base0 + 4096;  // next channel

    uint32_t outq[4], outk[4];
#pragma unroll
    for (int tsel = 0; tsel < 2; tsel++) {
        const float* src = tsel ? kv : q;
        float4 a00 = *(const float4*)(src + base0);
        float4 a01 = *(const float4*)(src + base0 + 4);
        float4 a10 = *(const float4*)(src + base0 + 64);
        float4 a11 = *(const float4*)(src + base0 + 68);
        float4 b00 = *(const float4*)(src + base1);
        float4 b01 = *(const float4*)(src + base1 + 4);
        float4 b10 = *(const float4*)(src + base1 + 64);
        float4 b11 = *(const float4*)(src + base1 + 68);
        float pA0 = 0.25f * (a00.x + a00.y + a10.x + a10.y);
        float pA1 = 0.25f * (a00.z + a00.w + a10.z + a10.w);
        float pA2 = 0.25f * (a01.x + a01.y + a11.x + a11.y);
        float pA3 = 0.25f * (a01.z + a01.w + a11.z + a11.w);
        float pB0 = 0.25f * (b00.x + b00.y + b10.x + b10.y);
        float pB1 = 0.25f * (b00.z + b00.w + b10.z + b10.w);
        float pB2 = 0.25f * (b01.x + b01.y + b11.x + b11.y);
        float pB3 = 0.25f * (b01.z + b01.w + b11.z + b11.w);
        uint32_t* dst = tsel ? outk : outq;
        dst[0] = pk(pA0, pB0); dst[1] = pk(pA1, pB1);
        dst[2] = pk(pA2, pB2); dst[3] = pk(pA3, pB3);
    }
    long off = ((long)(b * 128 + c2) << 10) + s;
    *(uint4*)&g_qp [off] = make_uint4(outq[0], outq[1], outq[2], outq[3]);
    *(uint4*)&g_kpx[off] = make_uint4(outk[0], outk[1], outk[2], outk[3]);
}

// ---------------------------------------------------------------------------
// bf16 GEMM body: Y[256][1024] = W @ X, block 128x128, 2-stage cp.async.
// ---------------------------------------------------------------------------
__device__ __forceinline__ void gemm_body(const uint32_t* __restrict__ Wk,
                                          const uint32_t* __restrict__ X,
                                          uint32_t Ws[2][16][136],
                                          uint32_t Xs[2][16][136],
                                          float acc[2][8][4],
                                          int m0, int n0)
{
    const int tid = threadIdx.x;
    const int w = tid >> 5, t = tid & 31, g = t >> 2, c = t & 3;
    const int wm = (w >> 1) * 32, wn = (w & 1) * 64;

#pragma unroll
    for (int mi = 0; mi < 2; mi++)
#pragma unroll
        for (int ni = 0; ni < 8; ni++)
#pragma unroll
            for (int r = 0; r < 4; r++) acc[mi][ni][r] = 0.f;

    auto stage = [&](int s, int kb) {
        uint32_t wb = smem_u32(&Ws[s][0][0]);
        uint32_t xb = smem_u32(&Xs[s][0][0]);
#pragma unroll
        for (int i = 0; i < 2; i++) {
            int id = tid + (i << 8);
            int r = id >> 5, col = (id & 31) << 2;
            cpa16(wb + (uint32_t)((r * 136 + col) << 2),
                  Wk + (kb * 16 + r) * 256 + m0 + col);
            cpa16(xb + (uint32_t)((r * 136 + col) << 2),
                  X + (kb * 16 + r) * 1024 + n0 + col);
        }
        cp_commit();
    };

    stage(0, 0);
    for (int kb = 0; kb < 8; kb++) {
        int cur = kb & 1;
        if (kb < 7) { stage(1 - cur, kb + 1); cp_wait1(); }
        else        { cp_wait0(); }
        __syncthreads();
#pragma unroll
        for (int ks = 0; ks < 2; ks++) {
            uint32_t a[2][4];
#pragma unroll
            for (int mi = 0; mi < 2; mi++) {
                int mb = wm + mi * 16;
                a[mi][0] = Ws[cur][8 * ks + c][mb + g];
                a[mi][1] = Ws[cur][8 * ks + c][mb + g + 8];
                a[mi][2] = Ws[cur][8 * ks + c + 4][mb + g];
                a[mi][3] = Ws[cur][8 * ks + c + 4][mb + g + 8];
            }
#pragma unroll
            for (int ni = 0; ni < 8; ni++) {
                uint32_t b0 = Xs[cur][8 * ks + c][wn + ni * 8 + g];
                uint32_t b1 = Xs[cur][8 * ks + c + 4][wn + ni * 8 + g];
                mma_bf16(acc[0][ni], a[0], b0, b1);
                mma_bf16(acc[1][ni], a[1], b0, b1);
            }
        }
        __syncthreads();
    }
}

// QKV epilogues: Q -> [c2][s]; K -> [s][c2] (LDSM layout); V -> [d][s2]
__global__ __launch_bounds__(256, 2) void gemm_qkv()
{
    __shared__ uint32_t Ws[2][16][136];
    __shared__ uint32_t Xs[2][16][136];
    int z = blockIdx.z;
    int b = z / 3, w3 = z - 3 * b;
    const uint32_t* Wk = g_Wk + w3 * 128 * 256;
    const uint32_t* X  = ((w3 == 0) ? g_qp : g_kpx) + b * 128 * 1024;
    int m0 = blockIdx.y * 128, n0 = blockIdx.x * 128;

    float acc[2][8][4];
    gemm_body(Wk, X, Ws, Xs, acc, m0, n0);

    const int tid = threadIdx.x;
    const int w = tid >> 5, t = tid & 31, g = t >> 2, c = t & 3;
    const int wm = (w >> 1) * 32, wn = (w & 1) * 64;

    if (w3 < 2) {
        bool even = (g & 1) == 0;
#pragma unroll
        for (int mi = 0; mi < 2; mi++) {
            int base = m0 + wm + mi * 16;
#pragma unroll
            for (int ni = 0; ni < 8; ni++) {
                float p0 = __shfl_xor_sync(0xffffffffu, acc[mi][ni][0], 4);
                float p1 = __shfl_xor_sync(0xffffffffu, acc[mi][ni][1], 4);
                float p2 = __shfl_xor_sync(0xffffffffu, acc[mi][ni][2], 4);
                float p3 = __shfl_xor_sync(0xffffffffu, acc[mi][ni][3], 4);
                uint32_t w0, w1; int d2;
                if (even) {
                    w0 = pk(acc[mi][ni][0], p0);
                    w1 = pk(acc[mi][ni][1], p1);
                    d2 = (base + g) >> 1;
                } else {
                    w0 = pk(p2, acc[mi][ni][2]);
                    w1 = pk(p3, acc[mi][ni][3]);
                    d2 = (base + 7 + g) >> 1;
                }
                int col = n0 + wn + ni * 8 + 2 * c;
                if (w3 == 0) {
                    uint32_t* Yp = g_Qp + b * 128 * 1024;
                    *(uint2*)&Yp[(long)d2 * 1024 + col] = make_uint2(w0, w1);
                } else {
                    uint32_t* Kp = g_Kp + (long)b * 1024 * 128;
                    Kp[(long)col * 128 + d2]       = w0;
                    Kp[(long)(col + 1) * 128 + d2] = w1;
                }
            }
        }
    } else {
        uint32_t* Vp = g_Vp + b * 256 * 512;
#pragma unroll
        for (int mi = 0; mi < 2; mi++) {
            int base = m0 + wm + mi * 16;
#pragma unroll
            for (int ni = 0; ni < 8; ni++) {
                int s2 = ((n0 + wn) >> 1) + ni * 4 + c;
                Vp[(long)(base + g) * 512 + s2]     = pk(acc[mi][ni][0], acc[mi][ni][1]);
                Vp[(long)(base + g + 8) * 512 + s2] = pk(acc[mi][ni][2], acc[mi][ni][3]);
            }
        }
    }
}

__global__ __launch_bounds__(256, 2) void gemm_o()
{
    __shared__ uint32_t Ws[2][16][136];
    __shared__ uint32_t Xs[2][16][136];
    int b = blockIdx.z;
    int m0 = blockIdx.y * 128, n0 = blockIdx.x * 128;
    float acc[2][8][4];
    gemm_body(g_Wk + 3 * 128 * 256, g_Osp + b * 128 * 1024, Ws, Xs, acc, m0, n0);

    const int tid = threadIdx.x;
    const int w = tid >> 5, t = tid & 31, g = t >> 2, c = t & 3;
    const int wm = (w >> 1) * 32, wn = (w & 1) * 64;
    float* Y = g_ys + (long)b * PLANE;
#pragma unroll
    for (int mi = 0; mi < 2; mi++) {
        int r = m0 + wm + mi * 16 + g;
#pragma unroll
        for (int ni = 0; ni < 8; ni++) {
            int col = n0 + wn + ni * 8 + 2 * c;
            *(float2*)(Y + (long)r * 1024 + col) =
                make_float2(acc[mi][ni][0], acc[mi][ni][1]);
            *(float2*)(Y + (long)(r + 8) * 1024 + col) =
                make_float2(acc[mi][ni][2], acc[mi][ni][3]);
        }
    }
}

// ---------------------------------------------------------------------------
// Flash attention, bf16 mma, 2-stage cp.async, LDSM fragments,
// shift-free base-2 softmax (bounded logits -> no overflow; exact math).
// ---------------------------------------------------------------------------
__global__ __launch_bounds__(256, 2) void attn_kernel()
{
    __shared__ uint32_t Ks[2][64][20];   // [key][d2] (16 words used, pad 20)
    __shared__ uint32_t Vs[2][32][36];   // [d][s2]

    const int b  = blockIdx.z;
    const int h  = blockIdx.y;
    const int qt = blockIdx.x;
    const int tid = threadIdx.x;
    const int w = tid >> 5, t = tid & 31, g = t >> 2, c = t & 3;
    const int q0 = qt * 128 + w * 16;

    const uint32_t* Qp = g_Qp + (long)(b * 128 + h * 16) * 1024;
    const uint32_t* Kp = g_Kp + (long)b * 1024 * 128;    // [s][c2]
    const uint32_t* Vp = g_Vp + (long)(b * 256 + h * 32) * 512;

    // Q fragments (scale*log2e folded into Wq)
    uint32_t qa[2][4];
#pragma unroll
    for (int ks = 0; ks < 2; ks++) {
        qa[ks][0] = Qp[(8 * ks + c) * 1024 + q0 + g];
        qa[ks][1] = Qp[(8 * ks + c) * 1024 + q0 + g + 8];
        qa[ks][2] = Qp[(8 * ks + c + 4) * 1024 + q0 + g];
        qa[ks][3] = Qp[(8 * ks + c + 4) * 1024 + q0 + g + 8];
    }

    float l0 = 0.f, l1 = 0.f;
    float o[4][4];
#pragma unroll
    for (int ni = 0; ni < 4; ni++)
#pragma unroll
        for (int r = 0; r < 4; r++) o[ni][r] = 0.f;

    // staging indices
    const int sk_key = tid >> 2, sk_j = (tid & 3) << 2;  // K: 64 keys x 4 chunks
    const int vr = tid >> 3, vc = (tid & 7) << 2;        // V: 32 d x 4 chunks
    const int kcol = h * 16;

    // per-thread LDSM address components: (row within 16, col-quad)
    const int lm8 = ((t >> 4) & 1) * 8 + (t & 7);   // row within pair-of-mats
    const int lc4 = ((t >> 3) & 1) * 4;             // column word offset

    auto stage = [&](int s, int k0) {
        cpa16(smem_u32(&Ks[s][sk_key][sk_j]),
              Kp + (long)(k0 + sk_key) * 128 + kcol + sk_j);
        cpa16(smem_u32(&Vs[s][vr][vc]),
              Vp + vr * 512 + (k0 >> 1) + vc);
        cp_commit();
    };

    stage(0, 0);
    for (int it = 0; it < 16; it++) {
        int cur = it & 1;
        if (it < 15) { stage(1 - cur, (it + 1) * 64); cp_wait1(); }
        else         { cp_wait0(); }
        __syncthreads();

        // S = Q K^T (base-2 logits), K b-frags via ldmatrix
        float S[8][4];
#pragma unroll
        for (int ni = 0; ni < 8; ni++)
#pragma unroll
            for (int r = 0; r < 4; r++) S[ni][r] = 0.f;
#pragma unroll
        for (int ks = 0; ks < 2; ks++) {
#pragma unroll
            for (int np = 0; np < 4; np++) {
                uint32_t b0, b1, b2, b3;
                ldsm4(b0, b1, b2, b3,
                      smem_u32(&Ks[cur][np * 16 + lm8][ks * 8 + lc4]));
                mma_bf16(S[2 * np],     qa[ks], b0, b1);
                mma_bf16(S[2 * np + 1], qa[ks], b2, b3);
            }
        }

        // shift-free exp2 + local l accumulation (no shfl per tile)
#pragma unroll
        for (int ni = 0; ni < 8; ni++) {
            S[ni][0] = ex2(S[ni][0]); l0 += S[ni][0];
            S[ni][1] = ex2(S[ni][1]); l0 += S[ni][1];
            S[ni][2] = ex2(S[ni][2]); l1 += S[ni][2];
            S[ni][3] = ex2(S[ni][3]); l1 += S[ni][3];
        }

        // P.V — P A-frags from S regs, V b-frags via ldmatrix
#pragma unroll
        for (int ks4 = 0; ks4 < 4; ks4++) {
            uint32_t pa[4];
            pa[0] = pk(S[2 * ks4][0],     S[2 * ks4][1]);
            pa[1] = pk(S[2 * ks4][2],     S[2 * ks4][3]);
            pa[2] = pk(S[2 * ks4 + 1][0], S[2 * ks4 + 1][1]);
            pa[3] = pk(S[2 * ks4 + 1][2], S[2 * ks4 + 1][3]);
#pragma unroll
            for (int nip = 0; nip < 2; nip++) {
                uint32_t v0, v1, v2, v3;
                ldsm4(v0, v1, v2, v3,
                      smem_u32(&Vs[cur][nip * 16 + lm8][ks4 * 8 + lc4]));
                mma_bf16(o[2 * nip],     pa, v0, v1);
                mma_bf16(o[2 * nip + 1], pa, v2, v3);
            }
        }
        __syncthreads();
    }

    // reduce l across the quad once, normalize, write g_Osp [c2][s]
    l0 += __shfl_xor_sync(0xffffffffu, l0, 1);
    l0 += __shfl_xor_sync(0xffffffffu, l0, 2);
    l1 += __shfl_xor_sync(0xffffffffu, l1, 1);
    l1 += __shfl_xor_sync(0xffffffffu, l1, 2);
    float inv0 = 1.f / l0, inv1 = 1.f / l1;
    uint32_t* Osp = g_Osp + (long)(b * 128 + h * 16) * 1024;
#pragma unroll
    for (int ni = 0; ni < 4; ni++) {
        int d2 = 4 * ni + c;
        Osp[(long)d2 * 1024 + q0 + g]     = pk(o[ni][0] * inv0, o[ni][1] * inv0);
        Osp[(long)d2 * 1024 + q0 + g + 8] = pk(o[ni][2] * inv1, o[ni][3] * inv1);
    }
}

// ---------------------------------------------------------------------------
// Final: bilinear 2x upsample + residual + BatchNorm(eval)
// ---------------------------------------------------------------------------
__global__ __launch_bounds__(256) void final_kernel(const float* __restrict__ query,
                                                    const float* __restrict__ gamma,
                                                    const float* __restrict__ beta,
                                                    const float* __restrict__ mean,
                                                    const float* __restrict__ var,
                                                    float* __restrict__ out)
{
    int idx = blockIdx.x * blockDim.x + threadIdx.x;
    if (idx >= Bb * 256 * 64 * 64) return;
    int x = idx & 63;
    int y = (idx >> 6) & 63;
    int c = (idx >> 12) & 255;
    int bc = idx >> 12;

    const float* ys = g_ys + (long)bc * 1024;

    int jy = y >> 1;
    int oy = (y & 1) ? min(jy + 1, 31) : max(jy - 1, 0);
    int jx = x >> 1;
    int ox = (x & 1) ? min(jx + 1, 31) : max(jx - 1, 0);

    float v00 = ys[jy * 32 + jx];
    float v01 = ys[jy * 32 + ox];
    float v10 = ys[oy * 32 + jx];
    float v11 = ys[oy * 32 + ox];
    float v = 0.75f * (0.75f * v00 + 0.25f * v01)
            + 0.25f * (0.75f * v10 + 0.25f * v11);

    float gg = gamma[c] * rsqrtf(var[c] + 1e-5f);
    float bb = beta[c] - mean[c] * gg;
    out[idx] = (v + query[idx]) * gg + bb;
}

// ---------------------------------------------------------------------------
extern "C" void kernel_launch(void* const* d_in, const int* in_sizes, int n_in,
                              void* d_out, int out_size)
{
    (void)in_sizes; (void)n_in; (void)out_size;
    const float* query = (const float*)d_in[0];
    const float* kv    = (const float*)d_in[1];
    const float* Wq    = (const float*)d_in[2];
    const float* Wk    = (const float*)d_in[3];
    const float* Wv    = (const float*)d_in[4];
    const float* Wo    = (const float*)d_in[5];
    const float* gamma = (const float*)d_in[6];
    const float* beta  = (const float*)d_in[7];
    const float* mean  = (const float*)d_in[8];
    const float* var   = (const float*)d_in[9];
    float* out = (float*)d_out;

    prep_w<<<512, 256>>>(Wq, Wk, Wv, Wo);
    pool_kernel<<<1024, 256>>>(query, kv);
    gemm_qkv<<<dim3(8, 2, 24), 256>>>();
    attn_kernel<<<dim3(8, 8, 8), 256>>>();
    gemm_o<<<dim3(8, 2, 8), 256>>>();
    final_kernel<<<(Bb * 256 * 64 * 64 + 255) / 256, 256>>>(query, gamma, beta, mean, var, out);
}

// round 7
// speedup vs baseline: 6.0236x; 1.2093x over previous
#include <cuda_runtime.h>
#include <math.h>
#include <stdint.h>

static constexpr int Bb    = 8;
static constexpr int PLANE = 256 * 1024;

// Scratch (static device globals; allocation-free per harness rules)
// packed fp16x2 activations (pairs along channel unless noted)
__device__ uint32_t g_qp [8 * 128 * 1024];  // [b][c2][s]
__device__ uint32_t g_kpx[8 * 128 * 1024];  // [b][c2][s]
__device__ uint32_t g_Qp [8 * 128 * 1024];  // [b][c2][s]
__device__ uint32_t g_Kp [8 * 1024 * 128];  // [b][s][c2]  (LDSM-friendly)
__device__ uint32_t g_Vp [8 * 256 * 512];   // [b][d][s2]  (pairs along s)
__device__ uint32_t g_Osp[8 * 128 * 1024];  // [b][c2][s]
__device__ float    g_ys [8 * 256 * 1024];  // Wo output (small grid), fp32
__device__ uint32_t g_Wk [4 * 128 * 256];   // weights k-major packed: [w][c2][o]

// ---------------------------------------------------------------------------
__device__ __forceinline__ uint32_t pk(float lo, float hi) {
    uint32_t r;
    asm("cvt.rn.f16x2.f32 %0, %1, %2;" : "=r"(r) : "f"(hi), "f"(lo));
    return r;
}
__device__ __forceinline__ uint32_t ex2h2(uint32_t x) {
    uint32_t r;
    asm("ex2.approx.f16x2 %0, %1;" : "=r"(r) : "r"(x));
    return r;
}
__device__ __forceinline__ void mma_f16(float* d, const uint32_t* a,
                                        uint32_t b0, uint32_t b1) {
    asm volatile(
        "mma.sync.aligned.m16n8k16.row.col.f32.f16.f16.f32 "
        "{%0,%1,%2,%3}, {%4,%5,%6,%7}, {%8,%9}, {%0,%1,%2,%3};"
        : "+f"(d[0]), "+f"(d[1]), "+f"(d[2]), "+f"(d[3])
        : "r"(a[0]), "r"(a[1]), "r"(a[2]), "r"(a[3]), "r"(b0), "r"(b1));
}
__device__ __forceinline__ void ldsm4(uint32_t& r0, uint32_t& r1,
                                      uint32_t& r2, uint32_t& r3, uint32_t addr) {
    asm volatile("ldmatrix.sync.aligned.m8n8.x4.shared.b16 {%0,%1,%2,%3}, [%4];"
                 : "=r"(r0), "=r"(r1), "=r"(r2), "=r"(r3) : "r"(addr));
}
__device__ __forceinline__ void cpa16(uint32_t dst, const void* src) {
    asm volatile("cp.async.cg.shared.global [%0], [%1], 16;" :: "r"(dst), "l"(src));
}
__device__ __forceinline__ void cp_commit() { asm volatile("cp.async.commit_group;"); }
__device__ __forceinline__ void cp_wait1()  { asm volatile("cp.async.wait_group 1;"); }
__device__ __forceinline__ void cp_wait0()  { asm volatile("cp.async.wait_group 0;"); }
__device__ __forceinline__ uint32_t smem_u32(const void* p) {
    return (uint32_t)__cvta_generic_to_shared(p);
}

// ---------------------------------------------------------------------------
// Merged prep: blocks [0,512) pack weights; blocks [512,1536) avg-pool.
// Wq gets scale*log2(e) folded in.
// ---------------------------------------------------------------------------
__global__ __launch_bounds__(256) void prep_pool(const float* __restrict__ Wq,
                                                 const float* __restrict__ Wk_,
                                                 const float* __restrict__ Wv,
                                                 const float* __restrict__ Wo,
                                                 const float* __restrict__ q,
                                                 const float* __restrict__ kv)
{
    if (blockIdx.x < 512) {
        int idx = blockIdx.x * 256 + threadIdx.x;   // 131072 total
        int w  = idx >> 15;
        int c2 = (idx >> 8) & 127;
        int o  = idx & 255;
        const float* W = (w == 0) ? Wq : (w == 1) ? Wk_ : (w == 2) ? Wv : Wo;
        float2 v = *(const float2*)(W + o * 256 + 2 * c2);
        if (w == 0) {
            const float qs = 0.17677669529663687f * 1.4426950408889634f;
            v.x *= qs; v.y *= qs;
        }
        g_Wk[(w * 128 + c2) * 256 + o] = pk(v.x, v.y);
        return;
    }
    int idx = (blockIdx.x - 512) * 256 + threadIdx.x;   // 262144 total
    int s4 = idx & 255;
    int c2 = (idx >> 8) & 127;
    int b  = idx >> 15;
    int s  = s4 << 2;
    int px = s & 31, py = s >> 5;

    long base0 = (((long)(b * 256 + 2 * c2)) * 64 + 2 * py) * 64 + 2 * px;
    long base1 = base0 + 4096;  // next channel

    uint32_t outq[4], outk[4];
#pragma unroll
    for (int tsel = 0; tsel < 2; tsel++) {
        const float* src = tsel ? kv : q;
        float4 a00 = *(const float4*)(src + base0);
        float4 a01 = *(const float4*)(src + base0 + 4);
        float4 a10 = *(const float4*)(src + base0 + 64);
        float4 a11 = *(const float4*)(src + base0 + 68);
        float4 b00 = *(const float4*)(src + base1);
        float4 b01 = *(const float4*)(src + base1 + 4);
        float4 b10 = *(const float4*)(src + base1 + 64);
        float4 b11 = *(const float4*)(src + base1 + 68);
        float pA0 = 0.25f * (a00.x + a00.y + a10.x + a10.y);
        float pA1 = 0.25f * (a00.z + a00.w + a10.z + a10.w);
        float pA2 = 0.25f * (a01.x + a01.y + a11.x + a11.y);
        float pA3 = 0.25f * (a01.z + a01.w + a11.z + a11.w);
        float pB0 = 0.25f * (b00.x + b00.y + b10.x + b10.y);
        float pB1 = 0.25f * (b00.z + b00.w + b10.z + b10.w);
        float pB2 = 0.25f * (b01.x + b01.y + b11.x + b11.y);
        float pB3 = 0.25f * (b01.z + b01.w + b11.z + b11.w);
        uint32_t* dst = tsel ? outk : outq;
        dst[0] = pk(pA0, pB0); dst[1] = pk(pA1, pB1);
        dst[2] = pk(pA2, pB2); dst[3] = pk(pA3, pB3);
    }
    long off = ((long)(b * 128 + c2) << 10) + s;
    *(uint4*)&g_qp [off] = make_uint4(outq[0], outq[1], outq[2], outq[3]);
    *(uint4*)&g_kpx[off] = make_uint4(outk[0], outk[1], outk[2], outk[3]);
}

// ---------------------------------------------------------------------------
// fp16 GEMM body: Y[256][1024] = W @ X, block 128x128, 2-stage cp.async.
// ---------------------------------------------------------------------------
__device__ __forceinline__ void gemm_body(const uint32_t* __restrict__ Wk,
                                          const uint32_t* __restrict__ X,
                                          uint32_t Ws[2][16][136],
                                          uint32_t Xs[2][16][136],
                                          float acc[2][8][4],
                                          int m0, int n0)
{
    const int tid = threadIdx.x;
    const int w = tid >> 5, t = tid & 31, g = t >> 2, c = t & 3;
    const int wm = (w >> 1) * 32, wn = (w & 1) * 64;

#pragma unroll
    for (int mi = 0; mi < 2; mi++)
#pragma unroll
        for (int ni = 0; ni < 8; ni++)
#pragma unroll
            for (int r = 0; r < 4; r++) acc[mi][ni][r] = 0.f;

    auto stage = [&](int s, int kb) {
        uint32_t wb = smem_u32(&Ws[s][0][0]);
        uint32_t xb = smem_u32(&Xs[s][0][0]);
#pragma unroll
        for (int i = 0; i < 2; i++) {
            int id = tid + (i << 8);
            int r = id >> 5, col = (id & 31) << 2;
            cpa16(wb + (uint32_t)((r * 136 + col) << 2),
                  Wk + (kb * 16 + r) * 256 + m0 + col);
            cpa16(xb + (uint32_t)((r * 136 + col) << 2),
                  X + (kb * 16 + r) * 1024 + n0 + col);
        }
        cp_commit();
    };

    stage(0, 0);
    for (int kb = 0; kb < 8; kb++) {
        int cur = kb & 1;
        if (kb < 7) { stage(1 - cur, kb + 1); cp_wait1(); }
        else        { cp_wait0(); }
        __syncthreads();
#pragma unroll
        for (int ks = 0; ks < 2; ks++) {
            uint32_t a[2][4];
#pragma unroll
            for (int mi = 0; mi < 2; mi++) {
                int mb = wm + mi * 16;
                a[mi][0] = Ws[cur][8 * ks + c][mb + g];
                a[mi][1] = Ws[cur][8 * ks + c][mb + g + 8];
                a[mi][2] = Ws[cur][8 * ks + c + 4][mb + g];
                a[mi][3] = Ws[cur][8 * ks + c + 4][mb + g + 8];
            }
#pragma unroll
            for (int ni = 0; ni < 8; ni++) {
                uint32_t b0 = Xs[cur][8 * ks + c][wn + ni * 8 + g];
                uint32_t b1 = Xs[cur][8 * ks + c + 4][wn + ni * 8 + g];
                mma_f16(acc[0][ni], a[0], b0, b1);
                mma_f16(acc[1][ni], a[1], b0, b1);
            }
        }
        __syncthreads();
    }
}

// QKV epilogues: Q -> [c2][s]; K -> [s][c2] (LDSM layout); V -> [d][s2]
__global__ __launch_bounds__(256, 2) void gemm_qkv()
{
    __shared__ uint32_t Ws[2][16][136];
    __shared__ uint32_t Xs[2][16][136];
    int z = blockIdx.z;
    int b = z / 3, w3 = z - 3 * b;
    const uint32_t* Wk = g_Wk + w3 * 128 * 256;
    const uint32_t* X  = ((w3 == 0) ? g_qp : g_kpx) + b * 128 * 1024;
    int m0 = blockIdx.y * 128, n0 = blockIdx.x * 128;

    float acc[2][8][4];
    gemm_body(Wk, X, Ws, Xs, acc, m0, n0);

    const int tid = threadIdx.x;
    const int w = tid >> 5, t = tid & 31, g = t >> 2, c = t & 3;
    const int wm = (w >> 1) * 32, wn = (w & 1) * 64;

    if (w3 < 2) {
        bool even = (g & 1) == 0;
#pragma unroll
        for (int mi = 0; mi < 2; mi++) {
            int base = m0 + wm + mi * 16;
#pragma unroll
            for (int ni = 0; ni < 8; ni++) {
                float p0 = __shfl_xor_sync(0xffffffffu, acc[mi][ni][0], 4);
                float p1 = __shfl_xor_sync(0xffffffffu, acc[mi][ni][1], 4);
                float p2 = __shfl_xor_sync(0xffffffffu, acc[mi][ni][2], 4);
                float p3 = __shfl_xor_sync(0xffffffffu, acc[mi][ni][3], 4);
                uint32_t w0, w1; int d2;
                if (even) {
                    w0 = pk(acc[mi][ni][0], p0);
                    w1 = pk(acc[mi][ni][1], p1);
                    d2 = (base + g) >> 1;
                } else {
                    w0 = pk(p2, acc[mi][ni][2]);
                    w1 = pk(p3, acc[mi][ni][3]);
                    d2 = (base + 7 + g) >> 1;
                }
                int col = n0 + wn + ni * 8 + 2 * c;
                if (w3 == 0) {
                    uint32_t* Yp = g_Qp + b * 128 * 1024;
                    *(uint2*)&Yp[(long)d2 * 1024 + col] = make_uint2(w0, w1);
                } else {
                    uint32_t* Kp = g_Kp + (long)b * 1024 * 128;
                    Kp[(long)col * 128 + d2]       = w0;
                    Kp[(long)(col + 1) * 128 + d2] = w1;
                }
            }
        }
    } else {
        uint32_t* Vp = g_Vp + b * 256 * 512;
#pragma unroll
        for (int mi = 0; mi < 2; mi++) {
            int base = m0 + wm + mi * 16;
#pragma unroll
            for (int ni = 0; ni < 8; ni++) {
                int s2 = ((n0 + wn) >> 1) + ni * 4 + c;
                Vp[(long)(base + g) * 512 + s2]     = pk(acc[mi][ni][0], acc[mi][ni][1]);
                Vp[(long)(base + g + 8) * 512 + s2] = pk(acc[mi][ni][2], acc[mi][ni][3]);
            }
        }
    }
}

__global__ __launch_bounds__(256, 2) void gemm_o()
{
    __shared__ uint32_t Ws[2][16][136];
    __shared__ uint32_t Xs[2][16][136];
    int b = blockIdx.z;
    int m0 = blockIdx.y * 128, n0 = blockIdx.x * 128;
    float acc[2][8][4];
    gemm_body(g_Wk + 3 * 128 * 256, g_Osp + b * 128 * 1024, Ws, Xs, acc, m0, n0);

    const int tid = threadIdx.x;
    const int w = tid >> 5, t = tid & 31, g = t >> 2, c = t & 3;
    const int wm = (w >> 1) * 32, wn = (w & 1) * 64;
    float* Y = g_ys + (long)b * PLANE;
#pragma unroll
    for (int mi = 0; mi < 2; mi++) {
        int r = m0 + wm + mi * 16 + g;
#pragma unroll
        for (int ni = 0; ni < 8; ni++) {
            int col = n0 + wn + ni * 8 + 2 * c;
            *(float2*)(Y + (long)r * 1024 + col) =
                make_float2(acc[mi][ni][0], acc[mi][ni][1]);
            *(float2*)(Y + (long)(r + 8) * 1024 + col) =
                make_float2(acc[mi][ni][2], acc[mi][ni][3]);
        }
    }
}

// ---------------------------------------------------------------------------
// Flash attention, fp16 mma, 2-stage cp.async, LDSM fragments,
// shift-free base-2 softmax with paired f16x2 exp; l via ones-MMA.
// ---------------------------------------------------------------------------
__global__ __launch_bounds__(256, 2) void attn_kernel()
{
    __shared__ uint32_t Ks[2][64][20];   // [key][d2] (16 words used, pad 20)
    __shared__ uint32_t Vs[2][32][36];   // [d][s2]

    const int b  = blockIdx.z;
    const int h  = blockIdx.y;
    const int qt = blockIdx.x;
    const int tid = threadIdx.x;
    const int w = tid >> 5, t = tid & 31, g = t >> 2, c = t & 3;
    const int q0 = qt * 128 + w * 16;
    const uint32_t ONESx2 = 0x3C003C00u;   // fp16 {1.0, 1.0}

    const uint32_t* Qp = g_Qp + (long)(b * 128 + h * 16) * 1024;
    const uint32_t* Kp = g_Kp + (long)b * 1024 * 128;    // [s][c2]
    const uint32_t* Vp = g_Vp + (long)(b * 256 + h * 32) * 512;

    // Q fragments (scale*log2e folded into Wq)
    uint32_t qa[2][4];
#pragma unroll
    for (int ks = 0; ks < 2; ks++) {
        qa[ks][0] = Qp[(8 * ks + c) * 1024 + q0 + g];
        qa[ks][1] = Qp[(8 * ks + c) * 1024 + q0 + g + 8];
        qa[ks][2] = Qp[(8 * ks + c + 4) * 1024 + q0 + g];
        qa[ks][3] = Qp[(8 * ks + c + 4) * 1024 + q0 + g + 8];
    }

    float lC[4] = {0.f, 0.f, 0.f, 0.f};   // row-sum accumulator (ones-MMA)
    float o[4][4];
#pragma unroll
    for (int ni = 0; ni < 4; ni++)
#pragma unroll
        for (int r = 0; r < 4; r++) o[ni][r] = 0.f;

    // staging indices
    const int sk_key = tid >> 2, sk_j = (tid & 3) << 2;  // K: 64 keys x 4 chunks
    const int vr = tid >> 3, vc = (tid & 7) << 2;        // V: 32 d x 4 chunks
    const int kcol = h * 16;

    const int lm8 = ((t >> 4) & 1) * 8 + (t & 7);
    const int lc4 = ((t >> 3) & 1) * 4;

    auto stage = [&](int s, int k0) {
        cpa16(smem_u32(&Ks[s][sk_key][sk_j]),
              Kp + (long)(k0 + sk_key) * 128 + kcol + sk_j);
        cpa16(smem_u32(&Vs[s][vr][vc]),
              Vp + vr * 512 + (k0 >> 1) + vc);
        cp_commit();
    };

    stage(0, 0);
    for (int it = 0; it < 16; it++) {
        int cur = it & 1;
        if (it < 15) { stage(1 - cur, (it + 1) * 64); cp_wait1(); }
        else         { cp_wait0(); }
        __syncthreads();

        // S = Q K^T (base-2 logits), K b-frags via ldmatrix
        float S[8][4];
#pragma unroll
        for (int ni = 0; ni < 8; ni++)
#pragma unroll
            for (int r = 0; r < 4; r++) S[ni][r] = 0.f;
#pragma unroll
        for (int ks = 0; ks < 2; ks++) {
#pragma unroll
            for (int np = 0; np < 4; np++) {
                uint32_t b0, b1, b2, b3;
                ldsm4(b0, b1, b2, b3,
                      smem_u32(&Ks[cur][np * 16 + lm8][ks * 8 + lc4]));
                mma_f16(S[2 * np],     qa[ks], b0, b1);
                mma_f16(S[2 * np + 1], qa[ks], b2, b3);
            }
        }

        // pack logits to f16x2, paired exp2 -> P fragments directly
        uint32_t P[8][2];
#pragma unroll
        for (int ni = 0; ni < 8; ni++) {
            P[ni][0] = ex2h2(pk(S[ni][0], S[ni][1]));
            P[ni][1] = ex2h2(pk(S[ni][2], S[ni][3]));
        }

        // P.V + l row-sum via ones-MMA
#pragma unroll
        for (int ks4 = 0; ks4 < 4; ks4++) {
            uint32_t pa[4];
            pa[0] = P[2 * ks4][0];
            pa[1] = P[2 * ks4][1];
            pa[2] = P[2 * ks4 + 1][0];
            pa[3] = P[2 * ks4 + 1][1];
            mma_f16(lC, pa, ONESx2, ONESx2);
#pragma unroll
            for (int nip = 0; nip < 2; nip++) {
                uint32_t v0, v1, v2, v3;
                ldsm4(v0, v1, v2, v3,
                      smem_u32(&Vs[cur][nip * 16 + lm8][ks4 * 8 + lc4]));
                mma_f16(o[2 * nip],     pa, v0, v1);
                mma_f16(o[2 * nip + 1], pa, v2, v3);
            }
        }
        __syncthreads();
    }

    // lC[0] = full row sum (row g), lC[2] = row g+8; no shfl needed
    float inv0 = 1.f / lC[0], inv1 = 1.f / lC[2];
    uint32_t* Osp = g_Osp + (long)(b * 128 + h * 16) * 1024;
#pragma unroll
    for (int ni = 0; ni < 4; ni++) {
        int d2 = 4 * ni + c;
        Osp[(long)d2 * 1024 + q0 + g]     = pk(o[ni][0] * inv0, o[ni][1] * inv0);
        Osp[(long)d2 * 1024 + q0 + g + 8] = pk(o[ni][2] * inv1, o[ni][3] * inv1);
    }
}

// ---------------------------------------------------------------------------
// Final: bilinear 2x upsample + residual + BatchNorm(eval); 4 px/thread
// ---------------------------------------------------------------------------
__global__ __launch_bounds__(256) void final_kernel(const float* __restrict__ query,
                                                    const float* __restrict__ gamma,
                                                    const float* __restrict__ beta,
                                                    const float* __restrict__ mean,
                                                    const float* __restrict__ var,
                                                    float* __restrict__ out)
{
    int idx = blockIdx.x * 256 + threadIdx.x;       // 2097152 total
    int x4 = (idx & 15) << 2;
    int y  = (idx >> 4) & 63;
    int bc = idx >> 10;
    int c  = bc & 255;

    const float* ys = g_ys + (long)bc * 1024;
    int jy = y >> 1;
    int oy = (y & 1) ? min(jy + 1, 31) : max(jy - 1, 0);
    const float* r0 = ys + jy * 32;
    const float* r1 = ys + oy * 32;

    float gg = gamma[c] * rsqrtf(var[c] + 1e-5f);
    float bb = beta[c] - mean[c] * gg;

    long qoff = ((long)bc * 64 + y) * 64 + x4;
    float4 qv = *(const float4*)(query + qoff);
    float qq[4] = {qv.x, qv.y, qv.z, qv.w};
    float res[4];
#pragma unroll
    for (int p = 0; p < 4; p++) {
        int x = x4 + p;
        int jx = x >> 1;
        int ox = (x & 1) ? min(jx + 1, 31) : max(jx - 1, 0);
        float v = 0.75f * (0.75f * r0[jx] + 0.25f * r0[ox])
                + 0.25f * (0.75f * r1[jx] + 0.25f * r1[ox]);
        res[p] = (v + qq[p]) * gg + bb;
    }
    *(float4*)(out + qoff) = make_float4(res[0], res[1], res[2], res[3]);
}

// ---------------------------------------------------------------------------
extern "C" void kernel_launch(void* const* d_in, const int* in_sizes, int n_in,
                              void* d_out, int out_size)
{
    (void)in_sizes; (void)n_in; (void)out_size;
    const float* query = (const float*)d_in[0];
    const float* kv    = (const float*)d_in[1];
    const float* Wq    = (const float*)d_in[2];
    const float* Wk    = (const float*)d_in[3];
    const float* Wv    = (const float*)d_in[4];
    const float* Wo    = (const float*)d_in[5];
    const float* gamma = (const float*)d_in[6];
    const float* beta  = (const float*)d_in[7];
    const float* mean  = (const float*)d_in[8];
    const float* var   = (const float*)d_in[9];
    float* out = (float*)d_out;

    prep_pool<<<1536, 256>>>(Wq, Wk, Wv, Wo, query, kv);
    gemm_qkv<<<dim3(8, 2, 24), 256>>>();
    attn_kernel<<<dim3(8, 8, 8), 256>>>();
    gemm_o<<<dim3(8, 2, 8), 256>>>();
    final_kernel<<<8192, 256>>>(query, gamma, beta, mean, var, out);
}